// round 7
// baseline (speedup 1.0000x reference)
#include <cuda_runtime.h>

// x: [B=16, C=256, H=32, W=32] viewed [BC=4096][HW=1024].
// x1[b,p,cij] = x[b,cij,p]; 30 layers of per-channel(p) BN+relu6 ODE.
// One CTA per channel; z̃ = z/alpha recursion; f32x2 packed math;
// relu6 via FFMA.SAT (r6 = sat(a/6·z + b/6), update scaled by 6·dt);
// warp reduction via shfl butterfly (redux.f32 not available on sm_103).

constexpr int HW = 1024;
constexpr int BC = 4096;
constexpr int NL = 30;

__device__ float g_xt[(size_t)HW * BC];
__device__ float g_yt[(size_t)HW * BC];

typedef unsigned long long u64;

__device__ __forceinline__ u64 pk2(float x, float y) {
    u64 r; asm("mov.b64 %0,{%1,%2};" : "=l"(r) : "f"(x), "f"(y)); return r;
}
__device__ __forceinline__ void upk2(u64 v, float& x, float& y) {
    asm("mov.b64 {%0,%1},%2;" : "=f"(x), "=f"(y) : "l"(v));
}
__device__ __forceinline__ u64 fma2(u64 a, u64 b, u64 c) {
    u64 d; asm("fma.rn.f32x2 %0,%1,%2,%3;" : "=l"(d) : "l"(a), "l"(b), "l"(c)); return d;
}
__device__ __forceinline__ u64 add2(u64 a, u64 b) {
    u64 d; asm("add.rn.f32x2 %0,%1,%2;" : "=l"(d) : "l"(a), "l"(b)); return d;
}
__device__ __forceinline__ u64 mul2(u64 a, u64 b) {
    u64 d; asm("mul.rn.f32x2 %0,%1,%2;" : "=l"(d) : "l"(a), "l"(b)); return d;
}
__device__ __forceinline__ float fma_sat(float a, float b, float c) {
    float d; asm("fma.rn.sat.f32 %0,%1,%2,%3;" : "=f"(d) : "f"(a), "f"(b), "f"(c)); return d;
}

// ---------------------------------------------------------------------------
// Scalar 32x32 tiled transpose (round-1 proven): out[c][r] = in[r][c]
// ---------------------------------------------------------------------------
template<int ROWS, int COLS>
__global__ __launch_bounds__(256) void tr_kernel(const float* __restrict__ in,
                                                 float* __restrict__ out) {
    __shared__ float tile[32][33];
    const int bx = blockIdx.x * 32;
    const int by = blockIdx.y * 32;
    const int tx = threadIdx.x, ty = threadIdx.y;
#pragma unroll
    for (int j = 0; j < 32; j += 8)
        tile[ty + j][tx] = in[(size_t)(by + ty + j) * COLS + (bx + tx)];
    __syncthreads();
#pragma unroll
    for (int j = 0; j < 32; j += 8)
        out[(size_t)(bx + ty + j) * ROWS + (by + tx)] = tile[tx][ty + j];
}

// ---------------------------------------------------------------------------
// Fused 30-layer ODE. One CTA per channel p, 256 threads.
// Thread t owns (cij=t, b=0..15) as 8 packed pairs. x1 parked in smem
// (private slots, no sync needed). Per-layer scalars precomputed in lay[].
// ---------------------------------------------------------------------------
__global__ __launch_bounds__(256, 6) void ode_kernel(
    const float* __restrict__ xt,        // [HW][BC]
    const float* __restrict__ dtg,       // [NL]
    const float* __restrict__ mats,      // [NL][256]
    const float* __restrict__ gamma,     // [HW]
    const float* __restrict__ beta,      // [HW]
    float* __restrict__ yt)              // [HW][BC]
{
    __shared__ float4 lay[NL];           // {c1_l, A_{l+1}, 6*dt_l*A_{l+1}, eps*A_l^2}
    __shared__ float2 sm_x1[8][256];     // x1 pairs, slot per thread
    __shared__ float2 red[8];
    __shared__ float2 bcv;               // {a/6, b/6}
    __shared__ float  sm_alpha;

    const int p = blockIdx.x;
    const int t = threadIdx.x;
    const int lane = t & 31;
    const int wid  = t >> 5;

    // --- per-layer scalar precompute ---
    if (t < NL) {
        float d = dtg[t];
        d = fminf(fmaxf(d, 0.0f), 6.0f);
        lay[t].x = 1.0f - d;             // c1
        lay[t].y = d;                    // stash dt
    }
    __syncthreads();
    if (t == 0) {
        float A = 1.0f;                  // 1/alpha running
        float P = 1.0f;                  // alpha running (prod c1)
        for (int l = 0; l < NL; ++l) {
            const float c1 = lay[l].x;
            const float d  = lay[l].y;
            const float eps = 1e-5f * A * A;
            const float An = __fdividef(A, c1);
            P *= c1;
            lay[l] = make_float4(c1, An, 6.0f * d * An, eps);
            A = An;
        }
        sm_alpha = P;
    }

    const float gm = gamma[p];
    const float bt = beta[p];
    const float* __restrict__ xp = xt + (size_t)p * BC + t;
    const float* __restrict__ mp = mats + t;

    // --- load x1, init z̃_1 = (1+m_0)*x1 ---
    float mt = mp[0];
    u64 z[8];
#pragma unroll
    for (int u = 0; u < 8; ++u) {
        const float a = xp[(2 * u) * 256];
        const float b = xp[(2 * u + 1) * 256];
        sm_x1[u][t] = make_float2(a, b);
        z[u] = pk2(fmaf(mt, a, a), fmaf(mt, b, b));
    }
    __syncthreads();                      // covers lay[] from t==0

    for (int l = 0; l < NL; ++l) {
        const float4 L = lay[l];          // LDS.128 broadcast
        const float mnx = (l < NL - 1) ? mp[(l + 1) * 256] : 1.0f;
        const float kps = fmaf(-L.x, mt, mnx) * L.y;   // (m' - c1*m) * A_{l+1}
        mt = mnx;
        const u64 kp   = pk2(kps, kps);
        const u64 dt6p = pk2(L.z, L.z);

        // stats on z̃
        u64 s2 = 0ull, q2 = 0ull;
#pragma unroll
        for (int u = 0; u < 8; ++u) {
            s2 = add2(s2, z[u]);
            q2 = fma2(z[u], z[u], q2);
        }
        float sx, sy, qx, qy;
        upk2(s2, sx, sy); upk2(q2, qx, qy);
        float s = sx + sy, q = qx + qy;
#pragma unroll
        for (int o = 16; o > 0; o >>= 1) {
            s += __shfl_xor_sync(0xffffffffu, s, o);
            q += __shfl_xor_sync(0xffffffffu, q, o);
        }
        if (lane == 0) red[wid] = make_float2(s, q);
        __syncthreads();
        if (wid == 0) {
            float S = 0.0f, Q = 0.0f;
            if (lane < 8) { const float2 rv = red[lane]; S = rv.x; Q = rv.y; }
#pragma unroll
            for (int o = 4; o > 0; o >>= 1) {
                S += __shfl_xor_sync(0xffffffffu, S, o);
                Q += __shfl_xor_sync(0xffffffffu, Q, o);
            }
            const float inv = 1.0f / 4096.0f;
            const float mu  = S * inv;
            const float va  = fmaf(-mu, mu, Q * inv);
            const float ap  = gm * rsqrtf(va + L.w);
            const float a6  = ap * (1.0f / 6.0f);
            const float b6  = fmaf(-mu, ap, bt) * (1.0f / 6.0f);
            if (lane == 0) bcv = make_float2(a6, b6);
        }
        __syncthreads();
        const float2 ab = bcv;

#pragma unroll
        for (int u = 0; u < 8; ++u) {
            float zx, zy; upk2(z[u], zx, zy);
            const float rx = fma_sat(zx, ab.x, ab.y);  // relu6/6 via FFMA.SAT
            const float ry = fma_sat(zy, ab.x, ab.y);
            z[u] = fma2(dt6p, pk2(rx, ry), z[u]);
            const float2 xv = sm_x1[u][t];
            z[u] = fma2(kp, pk2(xv.x, xv.y), z[u]);
        }
    }

    // out = alpha * z̃_final  (layer 29 used m'=1 so z̃ holds y + x1)
    const float al = sm_alpha;
    const u64 al2 = pk2(al, al);
    float* __restrict__ yp = yt + (size_t)p * BC + t;
#pragma unroll
    for (int u = 0; u < 8; ++u) {
        float ox, oy; upk2(mul2(z[u], al2), ox, oy);
        yp[(2 * u) * 256]     = ox;
        yp[(2 * u + 1) * 256] = oy;
    }
}

// ---------------------------------------------------------------------------
extern "C" void kernel_launch(void* const* d_in, const int* in_sizes, int n_in,
                              void* d_out, int out_size) {
    const float* x   = (const float*)d_in[0];   // [16,256,32,32]
    const float* dt  = (const float*)d_in[1];   // [30,1]
    const float* mat = (const float*)d_in[2];   // [30,1,1,16,16]
    const float* gm  = (const float*)d_in[3];   // [1024]
    const float* bt  = (const float*)d_in[4];   // [1024]
    float* out = (float*)d_out;                 // [16,256,32,32]

    float *xt, *yt;
    cudaGetSymbolAddress((void**)&xt, g_xt);
    cudaGetSymbolAddress((void**)&yt, g_yt);

    dim3 blk(32, 8);
    tr_kernel<BC, HW><<<dim3(HW / 32, BC / 32), blk>>>(x, xt);
    ode_kernel<<<HW, 256>>>(xt, dt, mat, gm, bt, yt);
    tr_kernel<HW, BC><<<dim3(BC / 32, HW / 32), blk>>>(yt, out);
}

// round 9
// speedup vs baseline: 1.1538x; 1.1538x over previous
#include <cuda_runtime.h>

// x: [B=16, C=256, H=32, W=32] viewed [BC=4096][HW=1024].
// x1[b,p,cij] = x[b,cij,p]; 30 layers of per-channel(p) BN+relu6 ODE.
// One CTA per channel; z̃ = z/alpha recursion; f32x2 packed math;
// relu6 via FFMA.SAT; x1 + z in registers; ONE barrier per layer
// (double-buffered reduction slots + redundant all-warp final reduce).
// Transposes: proven scalar 32x32 tiled version (8.6us each).

constexpr int HW = 1024;
constexpr int BC = 4096;
constexpr int NL = 30;

__device__ float g_xt[(size_t)HW * BC];
__device__ float g_yt[(size_t)HW * BC];

typedef unsigned long long u64;

__device__ __forceinline__ u64 pk2(float x, float y) {
    u64 r; asm("mov.b64 %0,{%1,%2};" : "=l"(r) : "f"(x), "f"(y)); return r;
}
__device__ __forceinline__ void upk2(u64 v, float& x, float& y) {
    asm("mov.b64 {%0,%1},%2;" : "=f"(x), "=f"(y) : "l"(v));
}
__device__ __forceinline__ u64 fma2(u64 a, u64 b, u64 c) {
    u64 d; asm("fma.rn.f32x2 %0,%1,%2,%3;" : "=l"(d) : "l"(a), "l"(b), "l"(c)); return d;
}
__device__ __forceinline__ u64 add2(u64 a, u64 b) {
    u64 d; asm("add.rn.f32x2 %0,%1,%2;" : "=l"(d) : "l"(a), "l"(b)); return d;
}
__device__ __forceinline__ u64 mul2(u64 a, u64 b) {
    u64 d; asm("mul.rn.f32x2 %0,%1,%2;" : "=l"(d) : "l"(a), "l"(b)); return d;
}
__device__ __forceinline__ float fma_sat(float a, float b, float c) {
    float d; asm("fma.rn.sat.f32 %0,%1,%2,%3;" : "=f"(d) : "f"(a), "f"(b), "f"(c)); return d;
}

// ---------------------------------------------------------------------------
// Scalar 32x32 tiled transpose (proven): out[c][r] = in[r][c]
// ---------------------------------------------------------------------------
template<int ROWS, int COLS>
__global__ __launch_bounds__(256) void tr_kernel(const float* __restrict__ in,
                                                 float* __restrict__ out) {
    __shared__ float tile[32][33];
    const int bx = blockIdx.x * 32;
    const int by = blockIdx.y * 32;
    const int tx = threadIdx.x, ty = threadIdx.y;
#pragma unroll
    for (int j = 0; j < 32; j += 8)
        tile[ty + j][tx] = in[(size_t)(by + ty + j) * COLS + (bx + tx)];
    __syncthreads();
#pragma unroll
    for (int j = 0; j < 32; j += 8)
        out[(size_t)(bx + ty + j) * ROWS + (by + tx)] = tile[tx][ty + j];
}

// ---------------------------------------------------------------------------
// Fused 30-layer ODE. One CTA per channel p, 256 threads.
// Thread t owns (cij=t, b=0..15) as 8 packed pairs; x1 and z in registers.
// One __syncthreads per layer; final cross-warp reduce done redundantly by
// every warp from double-buffered red[l&1][8].
// ---------------------------------------------------------------------------
__global__ __launch_bounds__(256, 4) void ode_kernel(
    const float* __restrict__ xt,        // [HW][BC]
    const float* __restrict__ dtg,       // [NL]
    const float* __restrict__ mats,      // [NL][256]
    const float* __restrict__ gamma,     // [HW]
    const float* __restrict__ beta,      // [HW]
    float* __restrict__ yt)              // [HW][BC]
{
    __shared__ float4 lay[NL];           // {c1_l, A_{l+1}, 6*dt_l*A_{l+1}, eps*A_l^2}
    __shared__ float2 red[2][8];
    __shared__ float  sm_alpha;

    const int p = blockIdx.x;
    const int t = threadIdx.x;
    const int lane = t & 31;
    const int wid  = t >> 5;

    // --- per-layer scalar precompute ---
    if (t < NL) {
        float d = dtg[t];
        d = fminf(fmaxf(d, 0.0f), 6.0f);
        lay[t].x = 1.0f - d;             // c1
        lay[t].y = d;                    // stash dt
    }
    __syncthreads();
    if (t == 0) {
        float A = 1.0f;                  // 1/alpha running
        float P = 1.0f;                  // alpha running (prod c1)
        for (int l = 0; l < NL; ++l) {
            const float c1 = lay[l].x;
            const float d  = lay[l].y;
            const float eps = 1e-5f * A * A;
            const float An = __fdividef(A, c1);
            P *= c1;
            lay[l] = make_float4(c1, An, 6.0f * d * An, eps);
            A = An;
        }
        sm_alpha = P;
    }

    const float gm = gamma[p];
    const float bt = beta[p];
    const float* __restrict__ xp = xt + (size_t)p * BC + t;
    const float* __restrict__ mp = mats + t;

    // --- load x1 to registers, init z̃_1 = (1+m_0)*x1 ---
    float mt = mp[0];
    u64 x1[8], z[8];
#pragma unroll
    for (int u = 0; u < 8; ++u) {
        const float a = xp[(2 * u) * 256];
        const float b = xp[(2 * u + 1) * 256];
        x1[u] = pk2(a, b);
        z[u]  = pk2(fmaf(mt, a, a), fmaf(mt, b, b));
    }
    __syncthreads();                      // covers lay[] / sm_alpha from t==0

    for (int l = 0; l < NL; ++l) {
        const float4 L = lay[l];          // LDS.128 broadcast
        const float mnx = (l < NL - 1) ? mp[(l + 1) * 256] : 1.0f;
        const float kps = fmaf(-L.x, mt, mnx) * L.y;   // (m' - c1*m) * A_{l+1}
        mt = mnx;
        const u64 kp   = pk2(kps, kps);
        const u64 dt6p = pk2(L.z, L.z);
        const int par  = l & 1;

        // stats on z̃ (packed accumulate)
        u64 s2 = 0ull, q2 = 0ull;
#pragma unroll
        for (int u = 0; u < 8; ++u) {
            s2 = add2(s2, z[u]);
            q2 = fma2(z[u], z[u], q2);
        }
        float sx, sy, qx, qy;
        upk2(s2, sx, sy); upk2(q2, qx, qy);
        float s = sx + sy, q = qx + qy;
#pragma unroll
        for (int o = 16; o > 0; o >>= 1) {
            s += __shfl_xor_sync(0xffffffffu, s, o);
            q += __shfl_xor_sync(0xffffffffu, q, o);
        }
        if (lane == 0) red[par][wid] = make_float2(s, q);
        __syncthreads();                  // the ONLY barrier this layer

        // redundant all-warp final reduce: each group of 8 lanes holds all
        // 8 warp partials; 3-level butterfly gives the full sum in every lane.
        const float2 rv = red[par][lane & 7];
        float S = rv.x, Q = rv.y;
#pragma unroll
        for (int o = 4; o > 0; o >>= 1) {
            S += __shfl_xor_sync(0xffffffffu, S, o);
            Q += __shfl_xor_sync(0xffffffffu, Q, o);
        }
        const float inv = 1.0f / 4096.0f;
        const float mu  = S * inv;
        const float va  = fmaf(-mu, mu, Q * inv);
        const float ap  = gm * rsqrtf(va + L.w);
        const float a6  = ap * (1.0f / 6.0f);
        const float b6  = fmaf(-mu, ap, bt) * (1.0f / 6.0f);

#pragma unroll
        for (int u = 0; u < 8; ++u) {
            float zx, zy; upk2(z[u], zx, zy);
            const float rx = fma_sat(zx, a6, b6);      // relu6/6 via FFMA.SAT
            const float ry = fma_sat(zy, a6, b6);
            z[u] = fma2(dt6p, pk2(rx, ry), z[u]);
            z[u] = fma2(kp, x1[u], z[u]);
        }
    }

    // out = alpha * z̃_final  (layer 29 used m'=1 so z̃ holds y + x1)
    const float al = sm_alpha;
    const u64 al2 = pk2(al, al);
    float* __restrict__ yp = yt + (size_t)p * BC + t;
#pragma unroll
    for (int u = 0; u < 8; ++u) {
        float ox, oy; upk2(mul2(z[u], al2), ox, oy);
        yp[(2 * u) * 256]     = ox;
        yp[(2 * u + 1) * 256] = oy;
    }
}

// ---------------------------------------------------------------------------
extern "C" void kernel_launch(void* const* d_in, const int* in_sizes, int n_in,
                              void* d_out, int out_size) {
    const float* x   = (const float*)d_in[0];   // [16,256,32,32]
    const float* dt  = (const float*)d_in[1];   // [30,1]
    const float* mat = (const float*)d_in[2];   // [30,1,1,16,16]
    const float* gm  = (const float*)d_in[3];   // [1024]
    const float* bt  = (const float*)d_in[4];   // [1024]
    float* out = (float*)d_out;                 // [16,256,32,32]

    float *xt, *yt;
    cudaGetSymbolAddress((void**)&xt, g_xt);
    cudaGetSymbolAddress((void**)&yt, g_yt);

    dim3 blk(32, 8);
    // x: [4096 x 1024] -> xt: [1024 x 4096]
    tr_kernel<BC, HW><<<dim3(HW / 32, BC / 32), blk>>>(x, xt);
    // fused 30-layer ODE, one CTA per channel
    ode_kernel<<<HW, 256>>>(xt, dt, mat, gm, bt, yt);
    // yt: [1024 x 4096] -> out: [4096 x 1024]
    tr_kernel<HW, BC><<<dim3(BC / 32, HW / 32), blk>>>(yt, out);
}